// round 10
// baseline (speedup 1.0000x reference)
#include <cuda_runtime.h>
#include <cuda_bf16.h>

namespace {
constexpr int Hc = 16;
constexpr int Sc = 2048;
constexpr int Dc = 128;
constexpr int BM = 64;
constexpr int BN = 64;
constexpr int NT = 256;

// dynamic smem layout (in floats)
constexpr int OFF_QT   = 0;      // Q^T swizzled  [d][ii]  128x64
constexpr int OFF_KV   = 8192;   // K^T swizzled (phase1) / V row-major (phase2)
constexpr int OFF_ST   = 16384;  // S^T swizzled  [jj][ii] 64x64
constexpr int OFF_ROWP = 20480;  // gamma^ii
constexpr int OFF_COLP = 20544;  // gamma^-jj
constexpr int OFF_INVL = 20608;  // 1/L for this block's 64 query rows
constexpr int SMEM_FLOATS = 20672;
constexpr int SMEM_BYTES  = SMEM_FLOATS * 4;   // 82688 B -> 2 CTAs/SM
}

__global__ __launch_bounds__(NT, 2)
void retention_fp32_kernel(const float* __restrict__ Qg,
                           const float* __restrict__ Kg,
                           const float* __restrict__ Vg,
                           float* __restrict__ Og)
{
    extern __shared__ float sm[];
    float* QT   = sm + OFF_QT;
    float* KV   = sm + OFF_KV;
    float* St   = sm + OFF_ST;
    float* rowp = sm + OFF_ROWP;
    float* colp = sm + OFF_COLP;
    float* invL = sm + OFF_INVL;

    const int tid = threadIdx.x;
    const int tx  = tid & 15;
    const int ty  = tid >> 4;
    const int a0  = ty * 4;          // query-row group within tile
    const int b0  = tx * 4;          // key-col group within tile

    const int qt  = (int)(gridDim.x - 1u - blockIdx.x);  // heavy tiles first
    const int h   = blockIdx.y;
    const int bb  = blockIdx.z;
    const int qi0 = qt * BM;

    const double g   = 1.0 - exp2(-(5.0 + (double)h));
    const double lg  = log2(g);
    const float  lgf = (float)lg;

    const size_t base = ((size_t)bb * Hc + h) * (size_t)Sc * Dc;
    const float* Qp = Qg + base;
    const float* Kp = Kg + base;
    const float* Vp = Vg + base;
    float*       Op = Og + base;

    // per-block tables
    if (tid < BM) {
        rowp[tid] = (float)exp2(lg * (double)tid);
        colp[tid] = (float)exp2(-lg * (double)tid);
        double gi1 = exp2(lg * (double)(qi0 + tid + 1));
        invL[tid] = (float)((1.0 - g) / (1.0 - gi1));   // 1/L, L=(1-g^{i+1})/(1-g)
    }
    __syncthreads();
    const float cp63 = colp[63];

    // Load Q^T (scaled by 1/L) into swizzled transposed smem.
    // element (d,row) stored at  d*64 + (row ^ ((d>>2 & 15)*4))
    #pragma unroll
    for (int it = 0; it < 8; ++it) {
        int idx = tid + it * NT;     // 0..2047
        int row = idx >> 5;
        int d4  = idx & 31;
        float4 v = *(const float4*)(Qp + (size_t)(qi0 + row) * Dc + d4 * 4);
        float scl = invL[row];
        int col = row ^ ((d4 & 15) * 4);
        float* dst = QT + d4 * 256 + col;   // d4*256 == (4*d4)*64
        dst[0]   = v.x * scl;
        dst[64]  = v.y * scl;
        dst[128] = v.z * scl;
        dst[192] = v.w * scl;
    }

    float o[4][8];                     // rows a0+r ; cols b0+c and 64+b0+c
    #pragma unroll
    for (int r = 0; r < 4; ++r)
        #pragma unroll
        for (int c = 0; c < 8; ++c) o[r][c] = 0.f;
    float rsum[4] = {0.f, 0.f, 0.f, 0.f};

    for (int kt = 0; kt <= qt; ++kt) {
        const int kj0 = kt * BN;
        const float tf = exp2f(lgf * (float)(qi0 - kj0));  // gamma^(qi0-kj0)
        if (tf * cp63 < 1e-12f) continue;   // uniform skip: tile contributes ~0

        __syncthreads();   // previous phase-2 done reading KV / St

        // ---- load K^T (transposed, swizzled) ----
        #pragma unroll
        for (int it = 0; it < 8; ++it) {
            int idx = tid + it * NT;
            int row = idx >> 5;
            int d4  = idx & 31;
            float4 v = *(const float4*)(Kp + (size_t)(kj0 + row) * Dc + d4 * 4);
            int col = row ^ ((d4 & 15) * 4);
            float* dst = KV + d4 * 256 + col;
            dst[0] = v.x; dst[64] = v.y; dst[128] = v.z; dst[192] = v.w;
        }
        __syncthreads();

        // ---- phase 1: S = (Q/L) . K^T  (inner dim d) ----
        float s[4][4];
        #pragma unroll
        for (int r = 0; r < 4; ++r)
            #pragma unroll
            for (int c = 0; c < 4; ++c) s[r][c] = 0.f;

        #pragma unroll 4
        for (int d = 0; d < 128; ++d) {
            const int sw = ((d >> 2) & 15) * 4;
            const float4 a  = *(const float4*)(QT + d * 64 + (a0 ^ sw));
            const float4 k4 = *(const float4*)(KV + d * 64 + (b0 ^ sw));
            s[0][0] += a.x * k4.x; s[0][1] += a.x * k4.y; s[0][2] += a.x * k4.z; s[0][3] += a.x * k4.w;
            s[1][0] += a.y * k4.x; s[1][1] += a.y * k4.y; s[1][2] += a.y * k4.z; s[1][3] += a.y * k4.w;
            s[2][0] += a.z * k4.x; s[2][1] += a.z * k4.y; s[2][2] += a.z * k4.z; s[2][3] += a.z * k4.w;
            s[3][0] += a.w * k4.x; s[3][1] += a.w * k4.y; s[3][2] += a.w * k4.z; s[3][3] += a.w * k4.w;
        }

        // ---- decay + causal mask + rowsum partials ----
        const bool diag = (kj0 == qi0);
        #pragma unroll
        for (int r = 0; r < 4; ++r) {
            const float rp = rowp[a0 + r] * tf;
            #pragma unroll
            for (int c = 0; c < 4; ++c) {
                float f = rp * colp[b0 + c];
                if (diag && (b0 + c > a0 + r)) f = 0.f;
                s[r][c] *= f;
            }
            rsum[r] += (s[r][0] + s[r][1]) + (s[r][2] + s[r][3]);
        }

        // ---- write S^T to smem, swizzled: (j,i) at j*64 + (i ^ ((j>>2 & 7)*4)) ----
        {
            const int swj = (tx & 7) * 4;   // (j>>2)&7 == tx&7 for j=b0+c
            #pragma unroll
            for (int c = 0; c < 4; ++c) {
                *(float4*)(St + (b0 + c) * 64 + (a0 ^ swj)) =
                    make_float4(s[0][c], s[1][c], s[2][c], s[3][c]);
            }
        }
        __syncthreads();   // St ready; all threads done reading KV-as-K

        // ---- load V (row-major) into KV ----
        #pragma unroll
        for (int it = 0; it < 8; ++it) {
            int idx = tid + it * NT;
            int row = idx >> 5;
            int c4  = idx & 31;
            *(float4*)(KV + row * 128 + c4 * 4) =
                *(const float4*)(Vp + (size_t)(kj0 + row) * Dc + c4 * 4);
        }
        __syncthreads();

        // ---- phase 2: O += S . V  (inner dim j) ----
        #pragma unroll 4
        for (int j = 0; j < 64; ++j) {
            const int swj = ((j >> 2) & 7) * 4;
            const float4 a  = *(const float4*)(St + j * 64 + (a0 ^ swj));
            const float4 v0 = *(const float4*)(KV + j * 128 + b0);
            const float4 v1 = *(const float4*)(KV + j * 128 + 64 + b0);
            o[0][0] += a.x * v0.x; o[0][1] += a.x * v0.y; o[0][2] += a.x * v0.z; o[0][3] += a.x * v0.w;
            o[0][4] += a.x * v1.x; o[0][5] += a.x * v1.y; o[0][6] += a.x * v1.z; o[0][7] += a.x * v1.w;
            o[1][0] += a.y * v0.x; o[1][1] += a.y * v0.y; o[1][2] += a.y * v0.z; o[1][3] += a.y * v0.w;
            o[1][4] += a.y * v1.x; o[1][5] += a.y * v1.y; o[1][6] += a.y * v1.z; o[1][7] += a.y * v1.w;
            o[2][0] += a.z * v0.x; o[2][1] += a.z * v0.y; o[2][2] += a.z * v0.z; o[2][3] += a.z * v0.w;
            o[2][4] += a.z * v1.x; o[2][5] += a.z * v1.y; o[2][6] += a.z * v1.z; o[2][7] += a.z * v1.w;
            o[3][0] += a.w * v0.x; o[3][1] += a.w * v0.y; o[3][2] += a.w * v0.z; o[3][3] += a.w * v0.w;
            o[3][4] += a.w * v1.x; o[3][5] += a.w * v1.y; o[3][6] += a.w * v1.z; o[3][7] += a.w * v1.w;
        }
    }

    // ---- reduce rowsums across the 16 column-threads (XOR<=8 stays within
    //      the 16-lane half-warp that shares ty, i.e. shares rows) ----
    #pragma unroll
    for (int off = 8; off > 0; off >>= 1) {
        #pragma unroll
        for (int r = 0; r < 4; ++r)
            rsum[r] += __shfl_xor_sync(0xffffffffu, rsum[r], off);
    }

    // ---- epilogue: P = max(|rowsum|, 1); O /= P; store ----
    #pragma unroll
    for (int r = 0; r < 4; ++r) {
        float p  = fmaxf(fabsf(rsum[r]), 1.0f);
        float ip = 1.0f / p;
        float* orow = Op + (size_t)(qi0 + a0 + r) * Dc;
        float4 w0 = make_float4(o[r][0] * ip, o[r][1] * ip, o[r][2] * ip, o[r][3] * ip);
        float4 w1 = make_float4(o[r][4] * ip, o[r][5] * ip, o[r][6] * ip, o[r][7] * ip);
        *(float4*)(orow + b0)      = w0;
        *(float4*)(orow + 64 + b0) = w1;
    }
}

extern "C" void kernel_launch(void* const* d_in, const int* in_sizes, int n_in,
                              void* d_out, int out_size)
{
    (void)n_in; (void)out_size;
    const float* q = (const float*)d_in[0];
    const float* k = (const float*)d_in[1];
    const float* v = (const float*)d_in[2];
    // d_in[3] (omask) intentionally unused: mask and L are computed analytically.
    float* o = (float*)d_out;

    const int Bdim = in_sizes[0] / (Hc * Sc * Dc);   // = 2

    cudaFuncSetAttribute(retention_fp32_kernel,
                         cudaFuncAttributeMaxDynamicSharedMemorySize, SMEM_BYTES);

    dim3 grid(Sc / BM, Hc, Bdim);
    retention_fp32_kernel<<<grid, NT, SMEM_BYTES>>>(q, k, v, o);
}

// round 11
// speedup vs baseline: 1.0139x; 1.0139x over previous
#include <cuda_runtime.h>
#include <cuda_bf16.h>

namespace {
constexpr int Hc = 16;
constexpr int Sc = 2048;
constexpr int Dc = 128;
constexpr int BM = 64;
constexpr int BN = 64;
constexpr int NT = 256;

// dynamic smem layout (in floats)
constexpr int OFF_QT   = 0;      // Q^T swizzled  [d][ii]  128x64
constexpr int OFF_KV   = 8192;   // K^T swizzled (phase1) / V row-major (phase2)
constexpr int OFF_ST   = 16384;  // S^T swizzled  [jj][ii] 64x64
constexpr int OFF_ROWP = 20480;  // gamma^ii
constexpr int OFF_COLP = 20544;  // gamma^-jj
constexpr int OFF_INVL = 20608;  // 1/L for this block's 64 query rows
constexpr int SMEM_FLOATS = 20672;
constexpr int SMEM_BYTES  = SMEM_FLOATS * 4;   // 82688 B -> 2 CTAs/SM
}

__global__ __launch_bounds__(NT, 2)
void retention_fp32_kernel(const float* __restrict__ Qg,
                           const float* __restrict__ Kg,
                           const float* __restrict__ Vg,
                           float* __restrict__ Og)
{
    extern __shared__ float sm[];
    float* QT   = sm + OFF_QT;
    float* KV   = sm + OFF_KV;
    float* St   = sm + OFF_ST;
    float* rowp = sm + OFF_ROWP;
    float* colp = sm + OFF_COLP;
    float* invL = sm + OFF_INVL;

    const int tid = threadIdx.x;
    const int tx  = tid & 15;
    const int ty  = tid >> 4;
    const int a0  = ty * 4;          // query-row group within tile
    const int b0  = tx * 4;          // key-col group within tile

    const int qt  = (int)(gridDim.x - 1u - blockIdx.x);  // heavy tiles first
    const int h   = blockIdx.y;
    const int bb  = blockIdx.z;
    const int qi0 = qt * BM;

    const double g   = 1.0 - exp2(-(5.0 + (double)h));
    const double lg  = log2(g);
    const float  lgf = (float)lg;

    const size_t base = ((size_t)bb * Hc + h) * (size_t)Sc * Dc;
    const float* Qp = Qg + base;
    const float* Kp = Kg + base;
    const float* Vp = Vg + base;
    float*       Op = Og + base;

    // per-block tables
    if (tid < BM) {
        rowp[tid] = (float)exp2(lg * (double)tid);
        colp[tid] = (float)exp2(-lg * (double)tid);
        double gi1 = exp2(lg * (double)(qi0 + tid + 1));
        invL[tid] = (float)((1.0 - g) / (1.0 - gi1));   // 1/L, L=(1-g^{i+1})/(1-g)
    }
    __syncthreads();
    const float cp63 = colp[63];

    // Load Q^T (scaled by 1/L) into swizzled transposed smem.
    // element (d,row) stored at  d*64 + (row ^ ((d>>2 & 15)*4))
    #pragma unroll
    for (int it = 0; it < 8; ++it) {
        int idx = tid + it * NT;     // 0..2047
        int row = idx >> 5;
        int d4  = idx & 31;
        float4 v = *(const float4*)(Qp + (size_t)(qi0 + row) * Dc + d4 * 4);
        float scl = invL[row];
        int col = row ^ ((d4 & 15) * 4);
        float* dst = QT + d4 * 256 + col;   // d4*256 == (4*d4)*64
        dst[0]   = v.x * scl;
        dst[64]  = v.y * scl;
        dst[128] = v.z * scl;
        dst[192] = v.w * scl;
    }

    float o[4][8];                     // rows a0+r ; cols b0+c and 64+b0+c
    #pragma unroll
    for (int r = 0; r < 4; ++r)
        #pragma unroll
        for (int c = 0; c < 8; ++c) o[r][c] = 0.f;
    float rsum[4] = {0.f, 0.f, 0.f, 0.f};

    for (int kt = 0; kt <= qt; ++kt) {
        const int kj0 = kt * BN;
        const float tf = exp2f(lgf * (float)(qi0 - kj0));  // gamma^(qi0-kj0)
        if (tf * cp63 < 1e-12f) continue;   // uniform skip: tile contributes ~0

        __syncthreads();   // previous phase-2 done reading KV / St

        // ---- load K^T (transposed, swizzled) ----
        #pragma unroll
        for (int it = 0; it < 8; ++it) {
            int idx = tid + it * NT;
            int row = idx >> 5;
            int d4  = idx & 31;
            float4 v = *(const float4*)(Kp + (size_t)(kj0 + row) * Dc + d4 * 4);
            int col = row ^ ((d4 & 15) * 4);
            float* dst = KV + d4 * 256 + col;
            dst[0] = v.x; dst[64] = v.y; dst[128] = v.z; dst[192] = v.w;
        }
        __syncthreads();

        // ---- phase 1: S = (Q/L) . K^T  (inner dim d) ----
        float s[4][4];
        #pragma unroll
        for (int r = 0; r < 4; ++r)
            #pragma unroll
            for (int c = 0; c < 4; ++c) s[r][c] = 0.f;

        #pragma unroll 4
        for (int d = 0; d < 128; ++d) {
            const int sw = ((d >> 2) & 15) * 4;
            const float4 a  = *(const float4*)(QT + d * 64 + (a0 ^ sw));
            const float4 k4 = *(const float4*)(KV + d * 64 + (b0 ^ sw));
            s[0][0] += a.x * k4.x; s[0][1] += a.x * k4.y; s[0][2] += a.x * k4.z; s[0][3] += a.x * k4.w;
            s[1][0] += a.y * k4.x; s[1][1] += a.y * k4.y; s[1][2] += a.y * k4.z; s[1][3] += a.y * k4.w;
            s[2][0] += a.z * k4.x; s[2][1] += a.z * k4.y; s[2][2] += a.z * k4.z; s[2][3] += a.z * k4.w;
            s[3][0] += a.w * k4.x; s[3][1] += a.w * k4.y; s[3][2] += a.w * k4.z; s[3][3] += a.w * k4.w;
        }

        // ---- decay + causal mask + rowsum partials ----
        const bool diag = (kj0 == qi0);
        #pragma unroll
        for (int r = 0; r < 4; ++r) {
            const float rp = rowp[a0 + r] * tf;
            #pragma unroll
            for (int c = 0; c < 4; ++c) {
                float f = rp * colp[b0 + c];
                if (diag && (b0 + c > a0 + r)) f = 0.f;
                s[r][c] *= f;
            }
            rsum[r] += (s[r][0] + s[r][1]) + (s[r][2] + s[r][3]);
        }

        // ---- write S^T to smem, swizzled: (j,i) at j*64 + (i ^ ((j>>2 & 7)*4)) ----
        {
            const int swj = (tx & 7) * 4;   // (j>>2)&7 == tx&7 for j=b0+c
            #pragma unroll
            for (int c = 0; c < 4; ++c) {
                *(float4*)(St + (b0 + c) * 64 + (a0 ^ swj)) =
                    make_float4(s[0][c], s[1][c], s[2][c], s[3][c]);
            }
        }
        __syncthreads();   // St ready; all threads done reading KV-as-K

        // ---- load V (row-major) into KV ----
        #pragma unroll
        for (int it = 0; it < 8; ++it) {
            int idx = tid + it * NT;
            int row = idx >> 5;
            int c4  = idx & 31;
            *(float4*)(KV + row * 128 + c4 * 4) =
                *(const float4*)(Vp + (size_t)(kj0 + row) * Dc + c4 * 4);
        }
        __syncthreads();

        // ---- phase 2: O += S . V  (inner dim j) ----
        #pragma unroll 4
        for (int j = 0; j < 64; ++j) {
            const int swj = ((j >> 2) & 7) * 4;
            const float4 a  = *(const float4*)(St + j * 64 + (a0 ^ swj));
            const float4 v0 = *(const float4*)(KV + j * 128 + b0);
            const float4 v1 = *(const float4*)(KV + j * 128 + 64 + b0);
            o[0][0] += a.x * v0.x; o[0][1] += a.x * v0.y; o[0][2] += a.x * v0.z; o[0][3] += a.x * v0.w;
            o[0][4] += a.x * v1.x; o[0][5] += a.x * v1.y; o[0][6] += a.x * v1.z; o[0][7] += a.x * v1.w;
            o[1][0] += a.y * v0.x; o[1][1] += a.y * v0.y; o[1][2] += a.y * v0.z; o[1][3] += a.y * v0.w;
            o[1][4] += a.y * v1.x; o[1][5] += a.y * v1.y; o[1][6] += a.y * v1.z; o[1][7] += a.y * v1.w;
            o[2][0] += a.z * v0.x; o[2][1] += a.z * v0.y; o[2][2] += a.z * v0.z; o[2][3] += a.z * v0.w;
            o[2][4] += a.z * v1.x; o[2][5] += a.z * v1.y; o[2][6] += a.z * v1.z; o[2][7] += a.z * v1.w;
            o[3][0] += a.w * v0.x; o[3][1] += a.w * v0.y; o[3][2] += a.w * v0.z; o[3][3] += a.w * v0.w;
            o[3][4] += a.w * v1.x; o[3][5] += a.w * v1.y; o[3][6] += a.w * v1.z; o[3][7] += a.w * v1.w;
        }
    }

    // ---- reduce rowsums across the 16 column-threads (XOR<=8 stays within
    //      the 16-lane half-warp that shares ty, i.e. shares rows) ----
    #pragma unroll
    for (int off = 8; off > 0; off >>= 1) {
        #pragma unroll
        for (int r = 0; r < 4; ++r)
            rsum[r] += __shfl_xor_sync(0xffffffffu, rsum[r], off);
    }

    // ---- epilogue: P = max(|rowsum|, 1); O /= P; store ----
    #pragma unroll
    for (int r = 0; r < 4; ++r) {
        float p  = fmaxf(fabsf(rsum[r]), 1.0f);
        float ip = 1.0f / p;
        float* orow = Op + (size_t)(qi0 + a0 + r) * Dc;
        float4 w0 = make_float4(o[r][0] * ip, o[r][1] * ip, o[r][2] * ip, o[r][3] * ip);
        float4 w1 = make_float4(o[r][4] * ip, o[r][5] * ip, o[r][6] * ip, o[r][7] * ip);
        *(float4*)(orow + b0)      = w0;
        *(float4*)(orow + 64 + b0) = w1;
    }
}

extern "C" void kernel_launch(void* const* d_in, const int* in_sizes, int n_in,
                              void* d_out, int out_size)
{
    (void)n_in; (void)out_size;
    const float* q = (const float*)d_in[0];
    const float* k = (const float*)d_in[1];
    const float* v = (const float*)d_in[2];
    // d_in[3] (omask) intentionally unused: mask and L are computed analytically.
    float* o = (float*)d_out;

    const int Bdim = in_sizes[0] / (Hc * Sc * Dc);   // = 2

    cudaFuncSetAttribute(retention_fp32_kernel,
                         cudaFuncAttributeMaxDynamicSharedMemorySize, SMEM_BYTES);

    dim3 grid(Sc / BM, Hc, Bdim);
    retention_fp32_kernel<<<grid, NT, SMEM_BYTES>>>(q, k, v, o);
}

// round 14
// speedup vs baseline: 2.7638x; 2.7260x over previous
#include <cuda_runtime.h>
#include <cstdint>

namespace {
constexpr int Hc = 16, Sc = 2048, Dc = 128;
constexpr int BM = 128, BN = 64, NT = 256;
constexpr int PQ = 272;   // Q/K smem row pitch (bytes) -> conflict-free frags
constexpr int PV = 144;   // Vt smem row pitch (bytes)

constexpr int QHI  = 0;
constexpr int QLO  = QHI + 128 * PQ;    // 34816
constexpr int KHI  = QLO + 128 * PQ;    // 69632
constexpr int KLO  = KHI + 64 * PQ;     // 87040
constexpr int VTH  = KLO + 64 * PQ;     // 104448
constexpr int VTL  = VTH + 128 * PV;    // 122880
constexpr int VSTG = VTL + 128 * PV;    // 141312 (fp32 64x128 staging)
constexpr int ROWP = VSTG + 32768;      // 174080
constexpr int COLP = ROWP + 512;
constexpr int INVL = COLP + 256;
constexpr int SMEM_BYTES = INVL + 512;  // 175360
} // namespace

__device__ __forceinline__ uint32_t pack2(float lo, float hi) {
    // low half <- lo, high half <- hi
    uint32_t r;
    asm("cvt.rn.satfinite.bf16x2.f32 %0, %1, %2;" : "=r"(r) : "f"(hi), "f"(lo));
    return r;
}
__device__ __forceinline__ float lo_f(uint32_t p) { return __uint_as_float(p << 16); }
__device__ __forceinline__ float hi_f(uint32_t p) { return __uint_as_float(p & 0xffff0000u); }

__device__ __forceinline__ void mma16816(float* c,
                                         uint32_t a0, uint32_t a1, uint32_t a2, uint32_t a3,
                                         uint32_t b0, uint32_t b1) {
    asm volatile(
        "mma.sync.aligned.m16n8k16.row.col.f32.bf16.bf16.f32 "
        "{%0,%1,%2,%3}, {%4,%5,%6,%7}, {%8,%9}, {%0,%1,%2,%3};"
        : "+f"(c[0]), "+f"(c[1]), "+f"(c[2]), "+f"(c[3])
        : "r"(a0), "r"(a1), "r"(a2), "r"(a3), "r"(b0), "r"(b1));
}

__global__ __launch_bounds__(NT, 1)
void retention_hmma_kernel(const float* __restrict__ Qg,
                           const float* __restrict__ Kg,
                           const float* __restrict__ Vg,
                           float* __restrict__ Og)
{
    extern __shared__ __align__(16) char smem[];
    float* rowp = (float*)(smem + ROWP);
    float* colp = (float*)(smem + COLP);
    float* invL = (float*)(smem + INVL);
    float* vstg = (float*)(smem + VSTG);

    const int tid  = threadIdx.x;
    const int w    = tid >> 5;
    const int lane = tid & 31;
    const int r    = lane >> 2;    // quad row
    const int cp   = lane & 3;     // quad col

    const int qt  = (int)(gridDim.x - 1u - blockIdx.x);  // heavy tiles first
    const int h   = blockIdx.y;
    const int bb  = blockIdx.z;
    const int qi0 = qt * BM;

    const double g   = 1.0 - exp2(-(5.0 + (double)h));
    const double lg  = log2(g);
    const float  lgf = (float)lg;

    const size_t base = ((size_t)bb * Hc + h) * (size_t)Sc * Dc;
    const float* Qp = Qg + base;
    const float* Kp = Kg + base;
    const float* Vp = Vg + base;
    float*       Op = Og + base;

    if (tid < 128) {
        rowp[tid] = (float)exp2(lg * (double)tid);
        invL[tid] = (float)((1.0 - g) / (1.0 - exp2(lg * (double)(qi0 + tid + 1))));
        if (tid < 64) colp[tid] = (float)exp2(-lg * (double)tid);
    }
    __syncthreads();
    const float cp63 = colp[63];

    // ---- Q convert: (Q * 1/L) -> hi/lo bf16, pitch-272 row-major ----
    #pragma unroll
    for (int it = 0; it < 16; ++it) {
        int idx = tid + it * NT;          // 0..4095
        int row = idx >> 5, d = (idx & 31) * 4;
        float4 v = *(const float4*)(Qp + (size_t)(qi0 + row) * Dc + d);
        float scl = invL[row];
        v.x *= scl; v.y *= scl; v.z *= scl; v.w *= scl;
        uint32_t h01 = pack2(v.x, v.y), h23 = pack2(v.z, v.w);
        uint32_t l01 = pack2(v.x - lo_f(h01), v.y - hi_f(h01));
        uint32_t l23 = pack2(v.z - lo_f(h23), v.w - hi_f(h23));
        *(uint2*)(smem + QHI + row * PQ + d * 2) = make_uint2(h01, h23);
        *(uint2*)(smem + QLO + row * PQ + d * 2) = make_uint2(l01, l23);
    }

    float o[16][4];
    #pragma unroll
    for (int nt = 0; nt < 16; ++nt) { o[nt][0] = 0.f; o[nt][1] = 0.f; o[nt][2] = 0.f; o[nt][3] = 0.f; }
    float rsum0 = 0.f, rsum1 = 0.f;

    const int   gr0 = 16 * w + r;           // local row of c0/c1 (c2/c3 at +8)
    const float rp0 = rowp[gr0], rp1 = rowp[gr0 + 8];
    const char* qhp = smem + QHI + gr0 * PQ;

    const int kthi = 2 * qt + 1;
    for (int kt = kthi; kt >= 0; --kt) {
        const int   kj0   = kt * BN;
        const int   dtile = qi0 - kj0;
        const float tf    = exp2f(lgf * (float)dtile);
        if (tf * cp63 < 1e-10f) break;   // decay monotone in this loop order

        __syncthreads();   // prev GEMM2 done reading Vt; Q writes visible (1st iter)

        // ---- K convert ----
        #pragma unroll
        for (int it = 0; it < 8; ++it) {
            int idx = tid + it * NT;
            int row = idx >> 5, d = (idx & 31) * 4;
            float4 v = *(const float4*)(Kp + (size_t)(kj0 + row) * Dc + d);
            uint32_t h01 = pack2(v.x, v.y), h23 = pack2(v.z, v.w);
            uint32_t l01 = pack2(v.x - lo_f(h01), v.y - hi_f(h01));
            uint32_t l23 = pack2(v.z - lo_f(h23), v.w - hi_f(h23));
            *(uint2*)(smem + KHI + row * PQ + d * 2) = make_uint2(h01, h23);
            *(uint2*)(smem + KLO + row * PQ + d * 2) = make_uint2(l01, l23);
        }
        // ---- V stage (swizzled fp32) ----
        #pragma unroll
        for (int it = 0; it < 8; ++it) {
            int idx = tid + it * NT;
            int j = idx >> 5, d4 = idx & 31;
            float4 v = *(const float4*)(Vp + (size_t)(kj0 + j) * Dc + d4 * 4);
            *(float4*)(vstg + j * 128 + ((d4 ^ (j & 7)) << 2)) = v;
        }
        __syncthreads();

        // ---- V transpose + split -> Vt[d][j] hi/lo bf16 ----
        {
            int d = tid & 127, jb = tid >> 7;
            #pragma unroll
            for (int q = 0; q < 4; ++q) {
                int jj0 = (jb + 2 * q) * 8;
                float f[8];
                #pragma unroll
                for (int k2 = 0; k2 < 8; ++k2)
                    f[k2] = vstg[(jj0 + k2) * 128 + (((d >> 2) ^ k2) << 2) + (d & 3)];
                uint32_t hh[4], ll[4];
                #pragma unroll
                for (int k2 = 0; k2 < 4; ++k2) {
                    hh[k2] = pack2(f[2 * k2], f[2 * k2 + 1]);
                    ll[k2] = pack2(f[2 * k2] - lo_f(hh[k2]), f[2 * k2 + 1] - hi_f(hh[k2]));
                }
                *(uint4*)(smem + VTH + d * PV + jj0 * 2) = make_uint4(hh[0], hh[1], hh[2], hh[3]);
                *(uint4*)(smem + VTL + d * PV + jj0 * 2) = make_uint4(ll[0], ll[1], ll[2], ll[3]);
            }
        }

        // ---- GEMM1: S[16x64] = Q(16x128) . K^T, 3-term split ----
        float s[8][4];
        #pragma unroll
        for (int jt = 0; jt < 8; ++jt) { s[jt][0] = 0.f; s[jt][1] = 0.f; s[jt][2] = 0.f; s[jt][3] = 0.f; }

        #pragma unroll
        for (int ks = 0; ks < 8; ++ks) {
            const int off = ks * 32 + cp * 4;
            uint32_t ah0 = *(const uint32_t*)(qhp + off);
            uint32_t ah1 = *(const uint32_t*)(qhp + 8 * PQ + off);
            uint32_t ah2 = *(const uint32_t*)(qhp + off + 16);
            uint32_t ah3 = *(const uint32_t*)(qhp + 8 * PQ + off + 16);
            uint32_t al0 = *(const uint32_t*)(qhp + (QLO - QHI) + off);
            uint32_t al1 = *(const uint32_t*)(qhp + (QLO - QHI) + 8 * PQ + off);
            uint32_t al2 = *(const uint32_t*)(qhp + (QLO - QHI) + off + 16);
            uint32_t al3 = *(const uint32_t*)(qhp + (QLO - QHI) + 8 * PQ + off + 16);
            #pragma unroll
            for (int jt = 0; jt < 8; ++jt) {
                const char* kb = smem + KHI + (jt * 8 + r) * PQ + off;
                uint32_t bh0 = *(const uint32_t*)(kb);
                uint32_t bh1 = *(const uint32_t*)(kb + 16);
                uint32_t bl0 = *(const uint32_t*)(kb + (KLO - KHI));
                uint32_t bl1 = *(const uint32_t*)(kb + (KLO - KHI) + 16);
                mma16816(s[jt], ah0, ah1, ah2, ah3, bh0, bh1);
                mma16816(s[jt], ah0, ah1, ah2, ah3, bl0, bl1);
                mma16816(s[jt], al0, al1, al2, al3, bh0, bh1);
            }
        }

        // ---- epilogue: decay + causal mask + rowsum; S -> A-frags (registers) ----
        uint32_t A2h[4][4], A2l[4][4];
        const float tfr0 = tf * rp0, tfr1 = tf * rp1;
        #pragma unroll
        for (int jt = 0; jt < 8; ++jt) {
            int j0 = jt * 8 + cp * 2;
            float c0 = colp[j0], c1 = colp[j0 + 1];
            float v00 = s[jt][0] * tfr0 * c0, v01 = s[jt][1] * tfr0 * c1;
            float v10 = s[jt][2] * tfr1 * c0, v11 = s[jt][3] * tfr1 * c1;
            if (dtile <= 0) {                 // diagonal / super-diagonal tiles
                if (j0     > gr0 + dtile)     v00 = 0.f;
                if (j0 + 1 > gr0 + dtile)     v01 = 0.f;
                if (j0     > gr0 + 8 + dtile) v10 = 0.f;
                if (j0 + 1 > gr0 + 8 + dtile) v11 = 0.f;
            }
            rsum0 += v00 + v01;
            rsum1 += v10 + v11;
            uint32_t p0 = pack2(v00, v01), p1 = pack2(v10, v11);
            int t = jt >> 1;
            if ((jt & 1) == 0) {
                A2h[t][0] = p0; A2h[t][1] = p1;
                A2l[t][0] = pack2(v00 - lo_f(p0), v01 - hi_f(p0));
                A2l[t][1] = pack2(v10 - lo_f(p1), v11 - hi_f(p1));
            } else {
                A2h[t][2] = p0; A2h[t][3] = p1;
                A2l[t][2] = pack2(v00 - lo_f(p0), v01 - hi_f(p0));
                A2l[t][3] = pack2(v10 - lo_f(p1), v11 - hi_f(p1));
            }
        }
        __syncthreads();   // Vt writes visible; K reads done before next overwrite

        // ---- GEMM2: O[16x128] += S(16x64) . V(64x128), 3-term split ----
        #pragma unroll
        for (int ks2 = 0; ks2 < 4; ++ks2) {
            const int off2 = ks2 * 32 + cp * 4;
            uint32_t a0 = A2h[ks2][0], a1 = A2h[ks2][1], a2 = A2h[ks2][2], a3 = A2h[ks2][3];
            uint32_t e0 = A2l[ks2][0], e1 = A2l[ks2][1], e2 = A2l[ks2][2], e3 = A2l[ks2][3];
            #pragma unroll
            for (int nt = 0; nt < 16; ++nt) {
                const char* vb = smem + VTH + (nt * 8 + r) * PV + off2;
                uint32_t bh0 = *(const uint32_t*)(vb);
                uint32_t bh1 = *(const uint32_t*)(vb + 16);
                uint32_t bl0 = *(const uint32_t*)(vb + (VTL - VTH));
                uint32_t bl1 = *(const uint32_t*)(vb + (VTL - VTH) + 16);
                mma16816(o[nt], a0, a1, a2, a3, bh0, bh1);
                mma16816(o[nt], a0, a1, a2, a3, bl0, bl1);
                mma16816(o[nt], e0, e1, e2, e3, bh0, bh1);
            }
        }
    }

    // ---- reduce rowsums within each quad (lanes share rows, differ in cp) ----
    #pragma unroll
    for (int off = 1; off < 4; off <<= 1) {
        rsum0 += __shfl_xor_sync(0xffffffffu, rsum0, off);
        rsum1 += __shfl_xor_sync(0xffffffffu, rsum1, off);
    }
    const float ip0 = 1.f / fmaxf(fabsf(rsum0), 1.f);
    const float ip1 = 1.f / fmaxf(fabsf(rsum1), 1.f);

    float* o0p = Op + (size_t)(qi0 + gr0) * Dc;
    float* o1p = Op + (size_t)(qi0 + gr0 + 8) * Dc;
    #pragma unroll
    for (int nt = 0; nt < 16; ++nt) {
        int col = nt * 8 + cp * 2;
        *(float2*)(o0p + col) = make_float2(o[nt][0] * ip0, o[nt][1] * ip0);
        *(float2*)(o1p + col) = make_float2(o[nt][2] * ip1, o[nt][3] * ip1);
    }
}

extern "C" void kernel_launch(void* const* d_in, const int* in_sizes, int n_in,
                              void* d_out, int out_size)
{
    (void)n_in; (void)out_size;
    const float* q = (const float*)d_in[0];
    const float* k = (const float*)d_in[1];
    const float* v = (const float*)d_in[2];
    // d_in[3] (omask) unused: decay mask and L computed analytically.
    float* o = (float*)d_out;

    const int Bdim = in_sizes[0] / (Hc * Sc * Dc);

    cudaFuncSetAttribute(retention_hmma_kernel,
                         cudaFuncAttributeMaxDynamicSharedMemorySize, SMEM_BYTES);

    dim3 grid(Sc / BM, Hc, Bdim);
    retention_hmma_kernel<<<grid, NT, SMEM_BYTES>>>(q, k, v, o);
}

// round 15
// speedup vs baseline: 2.8688x; 1.0380x over previous
#include <cuda_runtime.h>
#include <cstdint>

namespace {
constexpr int Hc = 16, Sc = 2048, Dc = 128;
constexpr int BM = 128, BN = 64, NT = 256;
constexpr int PQ = 272;   // K panel pitch (bytes) -> conflict-free B-frag LDS
constexpr int PV = 144;   // Vt panel pitch (bytes)

constexpr int KHI  = 0;
constexpr int KLO  = KHI + 64 * PQ;    // 17408
constexpr int VTH  = KLO + 64 * PQ;    // 34816
constexpr int VTL  = VTH + 128 * PV;   // 53248
constexpr int KSTG = VTL + 128 * PV;   // 71680  fp32 64x128 (cp.async dst)
constexpr int VSTG = KSTG + 32768;     // 104448 fp32 64x128 swizzled (cp.async dst)
constexpr int COLP = VSTG + 32768;     // 137216
constexpr int SMEM_BYTES = COLP + 256; // 137472
} // namespace

__device__ __forceinline__ uint32_t smem_u32(const void* p) {
    uint32_t a;
    asm("{ .reg .u64 t; cvta.to.shared.u64 t, %1; cvt.u32.u64 %0, t; }" : "=r"(a) : "l"(p));
    return a;
}
__device__ __forceinline__ uint32_t pack2(float lo, float hi) {
    uint32_t r;
    asm("cvt.rn.satfinite.bf16x2.f32 %0, %1, %2;" : "=r"(r) : "f"(hi), "f"(lo));
    return r;
}
__device__ __forceinline__ float lo_f(uint32_t p) { return __uint_as_float(p << 16); }
__device__ __forceinline__ float hi_f(uint32_t p) { return __uint_as_float(p & 0xffff0000u); }

__device__ __forceinline__ void mma16816(float* c,
                                         uint32_t a0, uint32_t a1, uint32_t a2, uint32_t a3,
                                         uint32_t b0, uint32_t b1) {
    asm volatile(
        "mma.sync.aligned.m16n8k16.row.col.f32.bf16.bf16.f32 "
        "{%0,%1,%2,%3}, {%4,%5,%6,%7}, {%8,%9}, {%0,%1,%2,%3};"
        : "+f"(c[0]), "+f"(c[1]), "+f"(c[2]), "+f"(c[3])
        : "r"(a0), "r"(a1), "r"(a2), "r"(a3), "r"(b0), "r"(b1));
}

#define CP16(dst, src)  asm volatile("cp.async.cg.shared.global [%0], [%1], 16;" :: "r"(dst), "l"(src) : "memory")
#define CP_COMMIT()     asm volatile("cp.async.commit_group;" ::: "memory")
#define CP_WAIT0()      asm volatile("cp.async.wait_group 0;" ::: "memory")

__global__ __launch_bounds__(NT, 1)
void retention_hmma2_kernel(const float* __restrict__ Qg,
                            const float* __restrict__ Kg,
                            const float* __restrict__ Vg,
                            float* __restrict__ Og)
{
    extern __shared__ __align__(16) char smem[];
    const uint32_t sb = smem_u32(smem);
    float* colp = (float*)(smem + COLP);
    float* vstg = (float*)(smem + VSTG);

    const int tid  = threadIdx.x;
    const int w    = tid >> 5;
    const int lane = tid & 31;
    const int r    = lane >> 2;
    const int cp   = lane & 3;

    const int qt  = (int)(gridDim.x - 1u - blockIdx.x);  // heavy tiles first
    const int h   = blockIdx.y;
    const int bb  = blockIdx.z;
    const int qi0 = qt * BM;

    const double g   = 1.0 - exp2(-(5.0 + (double)h));
    const double lg  = log2(g);
    const float  lgf = (float)lg;

    const size_t base = ((size_t)bb * Hc + h) * (size_t)Sc * Dc;
    const float* Qp = Qg + base;
    const float* Kp = Kg + base;
    const float* Vp = Vg + base;
    float*       Op = Og + base;

    if (tid < 64) colp[tid] = (float)exp2(-lg * (double)tid);

    const int   gr0   = 16 * w + r;
    const float rp0   = (float)exp2(lg * (double)gr0);
    const float rp1   = (float)exp2(lg * (double)(gr0 + 8));
    const float cp63f = (float)exp2(-lg * 63.0);

    // ---- prologue: prefetch first K/V tile via cp.async ----
    const int kthi = 2 * qt + 1;
    {
        const int kj0 = kthi * BN;
        #pragma unroll
        for (int it = 0; it < 8; ++it) {
            int idx = tid + it * NT;
            int j = idx >> 5, d4 = idx & 31;
            const float* src = Kp + (size_t)(kj0 + j) * Dc + d4 * 4;
            CP16(sb + KSTG + idx * 16, src);
            CP16(sb + VSTG + j * 512 + ((uint32_t)(d4 ^ (j & 7)) << 4),
                 Vp + (size_t)(kj0 + j) * Dc + d4 * 4);
        }
        CP_COMMIT();
    }

    // ---- Q A-fragments (hi/lo) in registers, scaled by 1/L ----
    uint32_t aQh[8][4], aQl[8][4];
    {
        const float f0 = (float)((1.0 - g) / (1.0 - exp2(lg * (double)(qi0 + gr0 + 1))));
        const float f1 = (float)((1.0 - g) / (1.0 - exp2(lg * (double)(qi0 + gr0 + 9))));
        const float* q0 = Qp + (size_t)(qi0 + gr0) * Dc;
        const float* q1 = Qp + (size_t)(qi0 + gr0 + 8) * Dc;
        #pragma unroll
        for (int ks = 0; ks < 8; ++ks) {
            int c0 = ks * 16 + cp * 2;
            float2 x0 = *(const float2*)(q0 + c0);
            float2 x1 = *(const float2*)(q1 + c0);
            float2 x2 = *(const float2*)(q0 + c0 + 8);
            float2 x3 = *(const float2*)(q1 + c0 + 8);
            x0.x *= f0; x0.y *= f0; x2.x *= f0; x2.y *= f0;
            x1.x *= f1; x1.y *= f1; x3.x *= f1; x3.y *= f1;
            aQh[ks][0] = pack2(x0.x, x0.y);
            aQl[ks][0] = pack2(x0.x - lo_f(aQh[ks][0]), x0.y - hi_f(aQh[ks][0]));
            aQh[ks][1] = pack2(x1.x, x1.y);
            aQl[ks][1] = pack2(x1.x - lo_f(aQh[ks][1]), x1.y - hi_f(aQh[ks][1]));
            aQh[ks][2] = pack2(x2.x, x2.y);
            aQl[ks][2] = pack2(x2.x - lo_f(aQh[ks][2]), x2.y - hi_f(aQh[ks][2]));
            aQh[ks][3] = pack2(x3.x, x3.y);
            aQl[ks][3] = pack2(x3.x - lo_f(aQh[ks][3]), x3.y - hi_f(aQh[ks][3]));
        }
    }

    float o[16][4];
    #pragma unroll
    for (int nt = 0; nt < 16; ++nt) { o[nt][0] = 0.f; o[nt][1] = 0.f; o[nt][2] = 0.f; o[nt][3] = 0.f; }
    float rsum0 = 0.f, rsum1 = 0.f;

    for (int kt = kthi; kt >= 0; --kt) {
        const int   kj0   = kt * BN;
        const int   dtile = qi0 - kj0;
        const float tf    = exp2f(lgf * (float)dtile);
        if (tf * cp63f < 1e-10f) { CP_WAIT0(); break; }   // decay monotone -> done

        CP_WAIT0();
        __syncthreads();   // staging ready; K/Vt panels free (prev GEMMs done)

        // ---- K convert: staging fp32 -> hi/lo bf16 panels ----
        #pragma unroll
        for (int it = 0; it < 8; ++it) {
            int idx = tid + it * NT;
            float4 v = *(const float4*)(smem + KSTG + idx * 16);
            int row = idx >> 5, d = (idx & 31) * 4;
            uint32_t h01 = pack2(v.x, v.y), h23 = pack2(v.z, v.w);
            uint32_t l01 = pack2(v.x - lo_f(h01), v.y - hi_f(h01));
            uint32_t l23 = pack2(v.z - lo_f(h23), v.w - hi_f(h23));
            *(uint2*)(smem + KHI + row * PQ + d * 2) = make_uint2(h01, h23);
            *(uint2*)(smem + KLO + row * PQ + d * 2) = make_uint2(l01, l23);
        }
        // ---- V transpose + split: staging -> Vt[d][j] hi/lo panels ----
        {
            int d = tid & 127, jb = tid >> 7;
            #pragma unroll
            for (int q2 = 0; q2 < 4; ++q2) {
                int jj0 = (jb + 2 * q2) * 8;
                float f[8];
                #pragma unroll
                for (int k2 = 0; k2 < 8; ++k2)
                    f[k2] = vstg[(jj0 + k2) * 128 + (((d >> 2) ^ k2) << 2) + (d & 3)];
                uint32_t hh[4], ll[4];
                #pragma unroll
                for (int k2 = 0; k2 < 4; ++k2) {
                    hh[k2] = pack2(f[2 * k2], f[2 * k2 + 1]);
                    ll[k2] = pack2(f[2 * k2] - lo_f(hh[k2]), f[2 * k2 + 1] - hi_f(hh[k2]));
                }
                *(uint4*)(smem + VTH + d * PV + jj0 * 2) = make_uint4(hh[0], hh[1], hh[2], hh[3]);
                *(uint4*)(smem + VTL + d * PV + jj0 * 2) = make_uint4(ll[0], ll[1], ll[2], ll[3]);
            }
        }
        __syncthreads();   // panels published; staging consumed

        // ---- prefetch next tile (overlaps the GEMMs below) ----
        {
            int nk = kt - 1;
            if (nk >= 0 && exp2f(lgf * (float)(qi0 - nk * BN)) * cp63f >= 1e-10f) {
                const int nj0 = nk * BN;
                #pragma unroll
                for (int it = 0; it < 8; ++it) {
                    int idx = tid + it * NT;
                    int j = idx >> 5, d4 = idx & 31;
                    CP16(sb + KSTG + idx * 16, Kp + (size_t)(nj0 + j) * Dc + d4 * 4);
                    CP16(sb + VSTG + j * 512 + ((uint32_t)(d4 ^ (j & 7)) << 4),
                         Vp + (size_t)(nj0 + j) * Dc + d4 * 4);
                }
            }
            CP_COMMIT();
        }

        // warps whose 16 rows are fully causal-masked skip all MMAs
        const bool wskip = (dtile < 0) && (16 * w + 15 + dtile < 0);
        if (wskip) continue;

        // ---- GEMM1: S[16x64] = Q . K^T, 3-term split (A in registers) ----
        float s[8][4];
        #pragma unroll
        for (int jt = 0; jt < 8; ++jt) { s[jt][0] = 0.f; s[jt][1] = 0.f; s[jt][2] = 0.f; s[jt][3] = 0.f; }

        #pragma unroll
        for (int ks = 0; ks < 8; ++ks) {
            const int off = ks * 32 + cp * 4;
            const uint32_t ah0 = aQh[ks][0], ah1 = aQh[ks][1], ah2 = aQh[ks][2], ah3 = aQh[ks][3];
            const uint32_t al0 = aQl[ks][0], al1 = aQl[ks][1], al2 = aQl[ks][2], al3 = aQl[ks][3];
            #pragma unroll
            for (int jt = 0; jt < 8; ++jt) {
                const char* kb = smem + KHI + (jt * 8 + r) * PQ + off;
                uint32_t bh0 = *(const uint32_t*)(kb);
                uint32_t bh1 = *(const uint32_t*)(kb + 16);
                uint32_t bl0 = *(const uint32_t*)(kb + (KLO - KHI));
                uint32_t bl1 = *(const uint32_t*)(kb + (KLO - KHI) + 16);
                mma16816(s[jt], ah0, ah1, ah2, ah3, bh0, bh1);
                mma16816(s[jt], ah0, ah1, ah2, ah3, bl0, bl1);
                mma16816(s[jt], al0, al1, al2, al3, bh0, bh1);
            }
        }

        // ---- epilogue: decay + causal mask + rowsum; S -> A-frags in regs ----
        uint32_t A2h[4][4], A2l[4][4];
        const float tfr0 = tf * rp0, tfr1 = tf * rp1;
        #pragma unroll
        for (int jt = 0; jt < 8; ++jt) {
            int j0 = jt * 8 + cp * 2;
            float c0 = colp[j0], c1 = colp[j0 + 1];
            float v00 = s[jt][0] * tfr0 * c0, v01 = s[jt][1] * tfr0 * c1;
            float v10 = s[jt][2] * tfr1 * c0, v11 = s[jt][3] * tfr1 * c1;
            if (dtile <= 0) {
                if (j0     > gr0 + dtile)     v00 = 0.f;
                if (j0 + 1 > gr0 + dtile)     v01 = 0.f;
                if (j0     > gr0 + 8 + dtile) v10 = 0.f;
                if (j0 + 1 > gr0 + 8 + dtile) v11 = 0.f;
            }
            rsum0 += v00 + v01;
            rsum1 += v10 + v11;
            uint32_t p0 = pack2(v00, v01), p1 = pack2(v10, v11);
            int t = jt >> 1;
            if ((jt & 1) == 0) {
                A2h[t][0] = p0; A2h[t][1] = p1;
                A2l[t][0] = pack2(v00 - lo_f(p0), v01 - hi_f(p0));
                A2l[t][1] = pack2(v10 - lo_f(p1), v11 - hi_f(p1));
            } else {
                A2h[t][2] = p0; A2h[t][3] = p1;
                A2l[t][2] = pack2(v00 - lo_f(p0), v01 - hi_f(p0));
                A2l[t][3] = pack2(v10 - lo_f(p1), v11 - hi_f(p1));
            }
        }

        // ---- GEMM2: O[16x128] += S . V (Vt panels already published) ----
        #pragma unroll
        for (int ks2 = 0; ks2 < 4; ++ks2) {
            const int off2 = ks2 * 32 + cp * 4;
            const uint32_t a0 = A2h[ks2][0], a1 = A2h[ks2][1], a2 = A2h[ks2][2], a3 = A2h[ks2][3];
            const uint32_t e0 = A2l[ks2][0], e1 = A2l[ks2][1], e2 = A2l[ks2][2], e3 = A2l[ks2][3];
            #pragma unroll
            for (int nt = 0; nt < 16; ++nt) {
                const char* vb = smem + VTH + (nt * 8 + r) * PV + off2;
                uint32_t bh0 = *(const uint32_t*)(vb);
                uint32_t bh1 = *(const uint32_t*)(vb + 16);
                uint32_t bl0 = *(const uint32_t*)(vb + (VTL - VTH));
                uint32_t bl1 = *(const uint32_t*)(vb + (VTL - VTH) + 16);
                mma16816(o[nt], a0, a1, a2, a3, bh0, bh1);
                mma16816(o[nt], a0, a1, a2, a3, bl0, bl1);
                mma16816(o[nt], e0, e1, e2, e3, bh0, bh1);
            }
        }
    }

    // ---- rowsum reduce within each quad; scale and store ----
    #pragma unroll
    for (int off = 1; off < 4; off <<= 1) {
        rsum0 += __shfl_xor_sync(0xffffffffu, rsum0, off);
        rsum1 += __shfl_xor_sync(0xffffffffu, rsum1, off);
    }
    const float ip0 = 1.f / fmaxf(fabsf(rsum0), 1.f);
    const float ip1 = 1.f / fmaxf(fabsf(rsum1), 1.f);

    float* o0p = Op + (size_t)(qi0 + gr0) * Dc;
    float* o1p = Op + (size_t)(qi0 + gr0 + 8) * Dc;
    #pragma unroll
    for (int nt = 0; nt < 16; ++nt) {
        int col = nt * 8 + cp * 2;
        *(float2*)(o0p + col) = make_float2(o[nt][0] * ip0, o[nt][1] * ip0);
        *(float2*)(o1p + col) = make_float2(o[nt][2] * ip1, o[nt][3] * ip1);
    }
}

extern "C" void kernel_launch(void* const* d_in, const int* in_sizes, int n_in,
                              void* d_out, int out_size)
{
    (void)n_in; (void)out_size;
    const float* q = (const float*)d_in[0];
    const float* k = (const float*)d_in[1];
    const float* v = (const float*)d_in[2];
    // d_in[3] (omask) unused: decay mask and L computed analytically.
    float* o = (float*)d_out;

    const int Bdim = in_sizes[0] / (Hc * Sc * Dc);

    cudaFuncSetAttribute(retention_hmma2_kernel,
                         cudaFuncAttributeMaxDynamicSharedMemorySize, SMEM_BYTES);

    dim3 grid(Sc / BM, Hc, Bdim);
    retention_hmma2_kernel<<<grid, NT, SMEM_BYTES>>>(q, k, v, o);
}

// round 16
// speedup vs baseline: 2.8949x; 1.0091x over previous
#include <cuda_runtime.h>
#include <cstdint>

namespace {
constexpr int Hc = 16, Sc = 2048, Dc = 128;
constexpr int BM = 128, BN = 64, NT = 256;
constexpr int PQ = 272;   // K panel pitch (bytes) -> conflict-free B-frag LDS
constexpr int PV = 144;   // Vt panel pitch (bytes)

constexpr int KHI  = 0;
constexpr int KLO  = KHI + 64 * PQ;    // 17408
constexpr int VTH  = KLO + 64 * PQ;    // 34816
constexpr int VTL  = VTH + 128 * PV;   // 53248
constexpr int KSTG = VTL + 128 * PV;   // 71680  fp32 64x128 (cp.async dst)
constexpr int VSTG = KSTG + 32768;     // 104448 fp32 64x128 swizzled (cp.async dst)
constexpr int COLP = VSTG + 32768;     // 137216
constexpr int SMEM_BYTES = COLP + 256; // 137472
} // namespace

__device__ __forceinline__ uint32_t smem_u32(const void* p) {
    uint32_t a;
    asm("{ .reg .u64 t; cvta.to.shared.u64 t, %1; cvt.u32.u64 %0, t; }" : "=r"(a) : "l"(p));
    return a;
}
__device__ __forceinline__ uint32_t pack2(float lo, float hi) {
    uint32_t r;
    asm("cvt.rn.satfinite.bf16x2.f32 %0, %1, %2;" : "=r"(r) : "f"(hi), "f"(lo));
    return r;
}
__device__ __forceinline__ float lo_f(uint32_t p) { return __uint_as_float(p << 16); }
__device__ __forceinline__ float hi_f(uint32_t p) { return __uint_as_float(p & 0xffff0000u); }

__device__ __forceinline__ void mma16816(float* c,
                                         uint32_t a0, uint32_t a1, uint32_t a2, uint32_t a3,
                                         uint32_t b0, uint32_t b1) {
    asm volatile(
        "mma.sync.aligned.m16n8k16.row.col.f32.bf16.bf16.f32 "
        "{%0,%1,%2,%3}, {%4,%5,%6,%7}, {%8,%9}, {%0,%1,%2,%3};"
        : "+f"(c[0]), "+f"(c[1]), "+f"(c[2]), "+f"(c[3])
        : "r"(a0), "r"(a1), "r"(a2), "r"(a3), "r"(b0), "r"(b1));
}

#define CP16(dst, src)  asm volatile("cp.async.cg.shared.global [%0], [%1], 16;" :: "r"(dst), "l"(src) : "memory")
#define CP_COMMIT()     asm volatile("cp.async.commit_group;" ::: "memory")
#define CP_WAIT0()      asm volatile("cp.async.wait_group 0;" ::: "memory")

__global__ __launch_bounds__(NT, 1)
void retention_hmma3_kernel(const float* __restrict__ Qg,
                            const float* __restrict__ Kg,
                            const float* __restrict__ Vg,
                            float* __restrict__ Og)
{
    extern __shared__ __align__(16) char smem[];
    const uint32_t sb = smem_u32(smem);
    float* colp = (float*)(smem + COLP);
    float* vstg = (float*)(smem + VSTG);

    const int tid  = threadIdx.x;
    const int w    = tid >> 5;
    const int lane = tid & 31;
    const int r    = lane >> 2;
    const int cp   = lane & 3;

    const int qt  = (int)(gridDim.x - 1u - blockIdx.x);  // heavy tiles first
    const int h   = blockIdx.y;
    const int bb  = blockIdx.z;
    const int qi0 = qt * BM;

    const double g   = 1.0 - exp2(-(5.0 + (double)h));
    const double lg  = log2(g);
    const float  lgf = (float)lg;

    const size_t base = ((size_t)bb * Hc + h) * (size_t)Sc * Dc;
    const float* Qp = Qg + base;
    const float* Kp = Kg + base;
    const float* Vp = Vg + base;
    float*       Op = Og + base;

    if (tid < 64) colp[tid] = (float)exp2(-lg * (double)tid);

    const int   gr0   = 16 * w + r;
    const float rp0   = (float)exp2(lg * (double)gr0);
    const float rp1   = (float)exp2(lg * (double)(gr0 + 8));
    const float cp63f = (float)exp2(-lg * 63.0);

    // ---- prologue: prefetch first K/V tile via cp.async ----
    const int kthi = 2 * qt + 1;
    {
        const int kj0 = kthi * BN;
        #pragma unroll
        for (int it = 0; it < 8; ++it) {
            int idx = tid + it * NT;
            int j = idx >> 5, d4 = idx & 31;
            CP16(sb + KSTG + idx * 16, Kp + (size_t)(kj0 + j) * Dc + d4 * 4);
            CP16(sb + VSTG + j * 512 + ((uint32_t)(d4 ^ (j & 7)) << 4),
                 Vp + (size_t)(kj0 + j) * Dc + d4 * 4);
        }
        CP_COMMIT();
    }

    // ---- Q A-fragments (hi/lo) in registers, scaled by 1/L ----
    uint32_t aQh[8][4], aQl[8][4];
    {
        const float f0 = (float)((1.0 - g) / (1.0 - exp2(lg * (double)(qi0 + gr0 + 1))));
        const float f1 = (float)((1.0 - g) / (1.0 - exp2(lg * (double)(qi0 + gr0 + 9))));
        const float* q0 = Qp + (size_t)(qi0 + gr0) * Dc;
        const float* q1 = Qp + (size_t)(qi0 + gr0 + 8) * Dc;
        #pragma unroll
        for (int ks = 0; ks < 8; ++ks) {
            int c0 = ks * 16 + cp * 2;
            float2 x0 = *(const float2*)(q0 + c0);
            float2 x1 = *(const float2*)(q1 + c0);
            float2 x2 = *(const float2*)(q0 + c0 + 8);
            float2 x3 = *(const float2*)(q1 + c0 + 8);
            x0.x *= f0; x0.y *= f0; x2.x *= f0; x2.y *= f0;
            x1.x *= f1; x1.y *= f1; x3.x *= f1; x3.y *= f1;
            aQh[ks][0] = pack2(x0.x, x0.y);
            aQl[ks][0] = pack2(x0.x - lo_f(aQh[ks][0]), x0.y - hi_f(aQh[ks][0]));
            aQh[ks][1] = pack2(x1.x, x1.y);
            aQl[ks][1] = pack2(x1.x - lo_f(aQh[ks][1]), x1.y - hi_f(aQh[ks][1]));
            aQh[ks][2] = pack2(x2.x, x2.y);
            aQl[ks][2] = pack2(x2.x - lo_f(aQh[ks][2]), x2.y - hi_f(aQh[ks][2]));
            aQh[ks][3] = pack2(x3.x, x3.y);
            aQl[ks][3] = pack2(x3.x - lo_f(aQh[ks][3]), x3.y - hi_f(aQh[ks][3]));
        }
    }

    float o[16][4];
    #pragma unroll
    for (int nt = 0; nt < 16; ++nt) { o[nt][0] = 0.f; o[nt][1] = 0.f; o[nt][2] = 0.f; o[nt][3] = 0.f; }
    float rsum0 = 0.f, rsum1 = 0.f;

    for (int kt = kthi; kt >= 0; --kt) {
        const int   kj0   = kt * BN;
        const int   dtile = qi0 - kj0;
        const float tf    = exp2f(lgf * (float)dtile);
        if (tf * cp63f < 1e-10f) { CP_WAIT0(); break; }   // decay monotone -> done

        CP_WAIT0();
        __syncthreads();   // staging ready; K/Vt panels free (prev GEMMs done)

        // ---- K convert: staging fp32 -> hi/lo bf16 panels ----
        #pragma unroll
        for (int it = 0; it < 8; ++it) {
            int idx = tid + it * NT;
            float4 v = *(const float4*)(smem + KSTG + idx * 16);
            int row = idx >> 5, d = (idx & 31) * 4;
            uint32_t h01 = pack2(v.x, v.y), h23 = pack2(v.z, v.w);
            uint32_t l01 = pack2(v.x - lo_f(h01), v.y - hi_f(h01));
            uint32_t l23 = pack2(v.z - lo_f(h23), v.w - hi_f(h23));
            *(uint2*)(smem + KHI + row * PQ + d * 2) = make_uint2(h01, h23);
            *(uint2*)(smem + KLO + row * PQ + d * 2) = make_uint2(l01, l23);
        }
        // ---- V transpose + split: staging -> Vt[d][j] hi/lo panels ----
        {
            int d = tid & 127, jb = tid >> 7;
            #pragma unroll
            for (int q2 = 0; q2 < 4; ++q2) {
                int jj0 = (jb + 2 * q2) * 8;
                float f[8];
                #pragma unroll
                for (int k2 = 0; k2 < 8; ++k2)
                    f[k2] = vstg[(jj0 + k2) * 128 + (((d >> 2) ^ k2) << 2) + (d & 3)];
                uint32_t hh[4], ll[4];
                #pragma unroll
                for (int k2 = 0; k2 < 4; ++k2) {
                    hh[k2] = pack2(f[2 * k2], f[2 * k2 + 1]);
                    ll[k2] = pack2(f[2 * k2] - lo_f(hh[k2]), f[2 * k2 + 1] - hi_f(hh[k2]));
                }
                *(uint4*)(smem + VTH + d * PV + jj0 * 2) = make_uint4(hh[0], hh[1], hh[2], hh[3]);
                *(uint4*)(smem + VTL + d * PV + jj0 * 2) = make_uint4(ll[0], ll[1], ll[2], ll[3]);
            }
        }
        __syncthreads();   // panels published; staging consumed

        // ---- prefetch next tile (overlaps the GEMMs below) ----
        {
            int nk = kt - 1;
            if (nk >= 0 && exp2f(lgf * (float)(qi0 - nk * BN)) * cp63f >= 1e-10f) {
                const int nj0 = nk * BN;
                #pragma unroll
                for (int it = 0; it < 8; ++it) {
                    int idx = tid + it * NT;
                    int j = idx >> 5, d4 = idx & 31;
                    CP16(sb + KSTG + idx * 16, Kp + (size_t)(nj0 + j) * Dc + d4 * 4);
                    CP16(sb + VSTG + j * 512 + ((uint32_t)(d4 ^ (j & 7)) << 4),
                         Vp + (size_t)(nj0 + j) * Dc + d4 * 4);
                }
            }
            CP_COMMIT();
        }

        // warps whose 16 rows are fully causal-masked skip all MMAs
        const bool wskip = (dtile < 0) && (16 * w + 15 + dtile < 0);
        if (wskip) continue;

        // ---- GEMM1: S[16x64] = Q . K^T, 3-term split, term-outer chunks ----
        float s[8][4];
        #pragma unroll
        for (int jt = 0; jt < 8; ++jt) { s[jt][0] = 0.f; s[jt][1] = 0.f; s[jt][2] = 0.f; s[jt][3] = 0.f; }

        #pragma unroll
        for (int ks = 0; ks < 8; ++ks) {
            const int off = ks * 32 + cp * 4;
            const uint32_t ah0 = aQh[ks][0], ah1 = aQh[ks][1], ah2 = aQh[ks][2], ah3 = aQh[ks][3];
            const uint32_t al0 = aQl[ks][0], al1 = aQl[ks][1], al2 = aQl[ks][2], al3 = aQl[ks][3];
            #pragma unroll
            for (int jc = 0; jc < 2; ++jc) {          // chunks of 4 accumulators
                uint32_t bh[4][2], bl[4][2];
                #pragma unroll
                for (int q2 = 0; q2 < 4; ++q2) {
                    const char* kb = smem + KHI + ((jc * 4 + q2) * 8 + r) * PQ + off;
                    bh[q2][0] = *(const uint32_t*)(kb);
                    bh[q2][1] = *(const uint32_t*)(kb + 16);
                    bl[q2][0] = *(const uint32_t*)(kb + (KLO - KHI));
                    bl[q2][1] = *(const uint32_t*)(kb + (KLO - KHI) + 16);
                }
                #pragma unroll
                for (int q2 = 0; q2 < 4; ++q2)
                    mma16816(s[jc * 4 + q2], ah0, ah1, ah2, ah3, bh[q2][0], bh[q2][1]);
                #pragma unroll
                for (int q2 = 0; q2 < 4; ++q2)
                    mma16816(s[jc * 4 + q2], ah0, ah1, ah2, ah3, bl[q2][0], bl[q2][1]);
                #pragma unroll
                for (int q2 = 0; q2 < 4; ++q2)
                    mma16816(s[jc * 4 + q2], al0, al1, al2, al3, bh[q2][0], bh[q2][1]);
            }
        }

        // ---- epilogue: decay + causal mask + rowsum; S -> A-frags in regs ----
        uint32_t A2h[4][4], A2l[4][4];
        const float tfr0 = tf * rp0, tfr1 = tf * rp1;
        #pragma unroll
        for (int jt = 0; jt < 8; ++jt) {
            int j0 = jt * 8 + cp * 2;
            float c0 = colp[j0], c1 = colp[j0 + 1];
            float v00 = s[jt][0] * tfr0 * c0, v01 = s[jt][1] * tfr0 * c1;
            float v10 = s[jt][2] * tfr1 * c0, v11 = s[jt][3] * tfr1 * c1;
            if (dtile <= 0) {
                if (j0     > gr0 + dtile)     v00 = 0.f;
                if (j0 + 1 > gr0 + dtile)     v01 = 0.f;
                if (j0     > gr0 + 8 + dtile) v10 = 0.f;
                if (j0 + 1 > gr0 + 8 + dtile) v11 = 0.f;
            }
            rsum0 += v00 + v01;
            rsum1 += v10 + v11;
            uint32_t p0 = pack2(v00, v01), p1 = pack2(v10, v11);
            int t = jt >> 1;
            if ((jt & 1) == 0) {
                A2h[t][0] = p0; A2h[t][1] = p1;
                A2l[t][0] = pack2(v00 - lo_f(p0), v01 - hi_f(p0));
                A2l[t][1] = pack2(v10 - lo_f(p1), v11 - hi_f(p1));
            } else {
                A2h[t][2] = p0; A2h[t][3] = p1;
                A2l[t][2] = pack2(v00 - lo_f(p0), v01 - hi_f(p0));
                A2l[t][3] = pack2(v10 - lo_f(p1), v11 - hi_f(p1));
            }
        }

        // ---- GEMM2: O[16x128] += S . V, 3-term split, term-outer chunks ----
        #pragma unroll
        for (int ks2 = 0; ks2 < 4; ++ks2) {
            const int off2 = ks2 * 32 + cp * 4;
            const uint32_t a0 = A2h[ks2][0], a1 = A2h[ks2][1], a2 = A2h[ks2][2], a3 = A2h[ks2][3];
            const uint32_t e0 = A2l[ks2][0], e1 = A2l[ks2][1], e2 = A2l[ks2][2], e3 = A2l[ks2][3];
            #pragma unroll
            for (int nc = 0; nc < 4; ++nc) {          // chunks of 4 accumulators
                uint32_t bh[4][2], bl[4][2];
                #pragma unroll
                for (int q2 = 0; q2 < 4; ++q2) {
                    const char* vb = smem + VTH + ((nc * 4 + q2) * 8 + r) * PV + off2;
                    bh[q2][0] = *(const uint32_t*)(vb);
                    bh[q2][1] = *(const uint32_t*)(vb + 16);
                    bl[q2][0] = *(const uint32_t*)(vb + (VTL - VTH));
                    bl[q2][1] = *(const uint32_t*)(vb + (VTL - VTH) + 16);
                }
                #pragma unroll
                for (int q2 = 0; q2 < 4; ++q2)
                    mma16816(o[nc * 4 + q2], a0, a1, a2, a3, bh[q2][0], bh[q2][1]);
                #pragma unroll
                for (int q2 = 0; q2 < 4; ++q2)
                    mma16816(o[nc * 4 + q2], a0, a1, a2, a3, bl[q2][0], bl[q2][1]);
                #pragma unroll
                for (int q2 = 0; q2 < 4; ++q2)
                    mma16816(o[nc * 4 + q2], e0, e1, e2, e3, bh[q2][0], bh[q2][1]);
            }
        }
    }

    // ---- rowsum reduce within each quad; scale and store ----
    #pragma unroll
    for (int off = 1; off < 4; off <<= 1) {
        rsum0 += __shfl_xor_sync(0xffffffffu, rsum0, off);
        rsum1 += __shfl_xor_sync(0xffffffffu, rsum1, off);
    }
    const float ip0 = 1.f / fmaxf(fabsf(rsum0), 1.f);
    const float ip1 = 1.f / fmaxf(fabsf(rsum1), 1.f);

    float* o0p = Op + (size_t)(qi0 + gr0) * Dc;
    float* o1p = Op + (size_t)(qi0 + gr0 + 8) * Dc;
    #pragma unroll
    for (int nt = 0; nt < 16; ++nt) {
        int col = nt * 8 + cp * 2;
        *(float2*)(o0p + col) = make_float2(o[nt][0] * ip0, o[nt][1] * ip0);
        *(float2*)(o1p + col) = make_float2(o[nt][2] * ip1, o[nt][3] * ip1);
    }
}

extern "C" void kernel_launch(void* const* d_in, const int* in_sizes, int n_in,
                              void* d_out, int out_size)
{
    (void)n_in; (void)out_size;
    const float* q = (const float*)d_in[0];
    const float* k = (const float*)d_in[1];
    const float* v = (const float*)d_in[2];
    // d_in[3] (omask) unused: decay mask and L computed analytically.
    float* o = (float*)d_out;

    const int Bdim = in_sizes[0] / (Hc * Sc * Dc);

    cudaFuncSetAttribute(retention_hmma3_kernel,
                         cudaFuncAttributeMaxDynamicSharedMemorySize, SMEM_BYTES);

    dim3 grid(Sc / BM, Hc, Bdim);
    retention_hmma3_kernel<<<grid, NT, SMEM_BYTES>>>(q, k, v, o);
}